// round 14
// baseline (speedup 1.0000x reference)
#include <cuda_runtime.h>

#define BB   32
#define LL   4096
#define IN   1024
#define QSZ  64
#define VSZ  256
#define HH   16
#define NCHUNK 16          // k_att blocks per batch (l-chunks of 256)
#define LCH  256
#define NSLOT 16           // one partial slot per chunk

#define QS_STRIDE 68
#define PSW   132          // psh row stride in 32-bit words
#define STG_L 8            // l-rows per cp.async stage (phase B)
#define NSTG  (LCH/STG_L)  // 32
#define DEPTH 4            // stage buffers
#define VS    260          // padded f32 per v row

// smem (words): qs 1088 + psh 2112 + wsum 128 + vt 4*8*260=8320 -> 45.5 KB
#define SMEM_WORDS (1088 + 2112 + 128 + DEPTH*STG_L*VS)
#define SMEM_BYTES (SMEM_WORDS * 4)

// Scratch (__device__ globals; no allocation allowed)
__device__ float g_q[BB*IN];                     // 128 KB
__device__ float g_partial[BB*NSLOT*HH*VSZ];     // 8 MB (unnormalized)
__device__ float g_s[BB*NSLOT*HH];               // per-slot expsum

// ---- mma helpers ----
__device__ __forceinline__ unsigned f2tf(float f) {
    unsigned u; asm("cvt.rna.tf32.f32 %0, %1;" : "=r"(u) : "f"(f)); return u;
}
__device__ __forceinline__ unsigned pack_h2(float lo, float hi) {
    unsigned d; asm("cvt.rn.f16x2.f32 %0, %1, %2;" : "=r"(d) : "f"(hi), "f"(lo)); return d;
}
__device__ __forceinline__ void mma_tf32(float& c0, float& c1, float& c2, float& c3,
                                         unsigned a0, unsigned a1, unsigned a2, unsigned a3,
                                         unsigned b0, unsigned b1) {
    asm("mma.sync.aligned.m16n8k8.row.col.f32.tf32.tf32.f32 "
        "{%0,%1,%2,%3}, {%4,%5,%6,%7}, {%8,%9}, {%0,%1,%2,%3};"
        : "+f"(c0), "+f"(c1), "+f"(c2), "+f"(c3)
        : "r"(a0), "r"(a1), "r"(a2), "r"(a3), "r"(b0), "r"(b1));
}
__device__ __forceinline__ void mma_f16(float& c0, float& c1, float& c2, float& c3,
                                        unsigned a0, unsigned a1, unsigned a2, unsigned a3,
                                        unsigned b0, unsigned b1) {
    asm("mma.sync.aligned.m16n8k16.row.col.f32.f16.f16.f32 "
        "{%0,%1,%2,%3}, {%4,%5,%6,%7}, {%8,%9}, {%0,%1,%2,%3};"
        : "+f"(c0), "+f"(c1), "+f"(c2), "+f"(c3)
        : "r"(a0), "r"(a1), "r"(a2), "r"(a3), "r"(b0), "r"(b1));
}
__device__ __forceinline__ void cp16(unsigned smem_addr, const void* gmem) {
    asm volatile("cp.async.cg.shared.global [%0], [%1], 16;" :: "r"(smem_addr), "l"(gmem));
}
__device__ __forceinline__ void cp_commit() {
    asm volatile("cp.async.commit_group;");
}
template <int N>
__device__ __forceinline__ void cp_wait() {
    asm volatile("cp.async.wait_group %0;" :: "n"(N));
}

// ============================================================
// K1: q[b,n] = query[b,:].Wq[n,:] + bq[n]
// Block: 4 n x 2 K-halves (8 warps) x 8 b. grid (256, 4).
// ============================================================
__global__ void __launch_bounds__(256) k_q(const float* __restrict__ query,
                                           const float* __restrict__ Wq,
                                           const float* __restrict__ bq) {
    __shared__ float qsm[8 * IN];
    __shared__ float ksum[8][8];
    int tid = threadIdx.x, lane = tid & 31, wid = tid >> 5;
    int nl = wid & 3, kh = wid >> 2;
    int n  = blockIdx.x * 4 + nl;
    int b0 = blockIdx.y * 8;

    const float4* qg = (const float4*)(query + (size_t)b0 * IN);
    float4* qs4 = (float4*)qsm;
    for (int i = tid; i < 8 * IN / 4; i += 256) qs4[i] = __ldg(qg + i);
    __syncthreads();

    const float4* w4 = (const float4*)(Wq + (size_t)n * IN) + kh * 128;
    float acc[8];
#pragma unroll
    for (int b = 0; b < 8; b++) acc[b] = 0.f;

#pragma unroll
    for (int it = 0; it < 4; it++) {
        int idx = it * 32 + lane;
        float4 w = __ldg(w4 + idx);
        int qi = kh * 128 + idx;
#pragma unroll
        for (int b = 0; b < 8; b++) {
            float4 q = qs4[b * (IN / 4) + qi];
            acc[b] += w.x * q.x + w.y * q.y + w.z * q.z + w.w * q.w;
        }
    }
#pragma unroll
    for (int b = 0; b < 8; b++) {
#pragma unroll
        for (int o = 16; o; o >>= 1) acc[b] += __shfl_xor_sync(0xffffffffu, acc[b], o);
    }
    if (lane == 0) {
#pragma unroll
        for (int b = 0; b < 8; b++) ksum[wid][b] = acc[b];
    }
    __syncthreads();
    if (tid < 32) {
        int nn = tid >> 3, bl = tid & 7;
        float v = ksum[nn][bl] + ksum[nn + 4][bl] + bq[blockIdx.x * 4 + nn];
        g_q[(size_t)(b0 + bl) * IN + blockIdx.x * 4 + nn] = v;
    }
}

// ============================================================
// K2: fused scores (tf32 MMA) + exp + pv (fp16 MMA, cp.async pipeline).
// Value prologue (stages 0,1) issued BEFORE phase A so the first 16.6KB
// of the value stream arrives while scores are being computed.
// ============================================================
__global__ void __launch_bounds__(256) k_att(const float* __restrict__ key,
                                             const float* __restrict__ value) {
    extern __shared__ float smx[];
    unsigned* qs   = (unsigned*)smx;           // [16 * 68] tf32 q
    unsigned* psh  = qs + HH * QS_STRIDE;      // [16 * 132] fp16x2 weights
    float*    wsum = (float*)(psh + HH * PSW); // [8*16]
    float*    vt   = wsum + 8 * HH;            // [DEPTH * 8 * 260]

    int b = blockIdx.y, c = blockIdx.x;
    int tid = threadIdx.x, lane = tid & 31, w = tid >> 5;
    int qr = lane >> 2, qc = lane & 3;

    const float* vb = value + ((size_t)b * LL + (size_t)c * LCH) * VSZ;
    unsigned vt_u = (unsigned)__cvta_generic_to_shared(vt);
    int r0 = tid >> 6, c4a = tid & 63;
    int r1 = r0 + 4;

    // ---- value prologue: stages 0,1 in flight during all of phase A ----
#pragma unroll
    for (int s = 0; s < 2; s++) {
        unsigned base = vt_u + (unsigned)(s * STG_L * VS) * 4u;
        cp16(base + (unsigned)(r0 * VS + c4a * 4) * 4u,
             vb + (size_t)(s * STG_L + r0) * VSZ + c4a * 4);
        cp16(base + (unsigned)(r1 * VS + c4a * 4) * 4u,
             vb + (size_t)(s * STG_L + r1) * VSZ + c4a * 4);
        cp_commit();
    }

    for (int i = tid; i < HH * QSZ; i += 256) {
        int h = i >> 6, d = i & 63;
        qs[h * QS_STRIDE + d] = f2tf(g_q[(size_t)b * IN + i]);
    }
    __syncthreads();

    // ---- Phase A: scores = q @ key^T (tf32), warp owns 32 l ----
    {
        int l0w = w * 32;
        const float* kb = key + ((size_t)b * LL + (size_t)c * LCH) * QSZ;
        float acc[4][4];
#pragma unroll
        for (int t = 0; t < 4; t++)
#pragma unroll
            for (int j = 0; j < 4; j++) acc[t][j] = 0.f;

#pragma unroll
        for (int k0 = 0; k0 < QSZ; k0 += 8) {
            unsigned a0 = qs[qr * QS_STRIDE + k0 + qc];
            unsigned a1 = qs[(qr + 8) * QS_STRIDE + k0 + qc];
            unsigned a2 = qs[qr * QS_STRIDE + k0 + qc + 4];
            unsigned a3 = qs[(qr + 8) * QS_STRIDE + k0 + qc + 4];
#pragma unroll
            for (int t = 0; t < 4; t++) {
                int l = l0w + t * 8 + qr;
                unsigned b0 = f2tf(__ldg(kb + (size_t)l * QSZ + k0 + qc));
                unsigned b1 = f2tf(__ldg(kb + (size_t)l * QSZ + k0 + qc + 4));
                mma_tf32(acc[t][0], acc[t][1], acc[t][2], acc[t][3],
                         a0, a1, a2, a3, b0, b1);
            }
        }

        float slo = 0.f, shi = 0.f;
#pragma unroll
        for (int t = 0; t < 4; t++) {
            int lb = l0w + t * 8 + 2 * qc;
            float e0 = __expf(acc[t][0] * 0.125f);
            float e1 = __expf(acc[t][1] * 0.125f);
            float e2 = __expf(acc[t][2] * 0.125f);
            float e3 = __expf(acc[t][3] * 0.125f);
            slo += e0 + e1;
            shi += e2 + e3;
            psh[qr * PSW + (lb >> 1)]       = pack_h2(e0, e1);
            psh[(qr + 8) * PSW + (lb >> 1)] = pack_h2(e2, e3);
        }
        slo += __shfl_xor_sync(0xffffffffu, slo, 1);
        slo += __shfl_xor_sync(0xffffffffu, slo, 2);
        shi += __shfl_xor_sync(0xffffffffu, shi, 1);
        shi += __shfl_xor_sync(0xffffffffu, shi, 2);
        if (qc == 0) {
            wsum[w * HH + qr]     = slo;
            wsum[w * HH + qr + 8] = shi;
        }
    }
    __syncthreads();
    if (tid < HH) {
        float S = 0.f;
#pragma unroll
        for (int i = 0; i < 8; i++) S += wsum[i * HH + tid];
        g_s[((size_t)b * NSLOT + c) * HH + tid] = S;
    }

    // ---- Phase B: pv = p @ v (fp16 MMA), 16 iterations of 16 l ----
    {
        int d0w = w * 32;
        float acc[4][4];
#pragma unroll
        for (int t = 0; t < 4; t++)
#pragma unroll
            for (int j = 0; j < 4; j++) acc[t][j] = 0.f;

        for (int si = 0; si < NSTG / 2; si++) {
#pragma unroll
            for (int ss = 0; ss < 2; ss++) {
                int s = 2 * si + 2 + ss;
                if (s < NSTG) {
                    unsigned base = vt_u + (unsigned)((s & 3) * STG_L * VS) * 4u;
                    cp16(base + (unsigned)(r0 * VS + c4a * 4) * 4u,
                         vb + (size_t)(s * STG_L + r0) * VSZ + c4a * 4);
                    cp16(base + (unsigned)(r1 * VS + c4a * 4) * 4u,
                         vb + (size_t)(s * STG_L + r1) * VSZ + c4a * 4);
                }
                cp_commit();
            }
            cp_wait<2>();
            __syncthreads();

            int bufA = (2 * si) & 3, bufB = (2 * si + 1) & 3;
            int Lw = si * 8;
            unsigned a0 = psh[qr * PSW + Lw + qc];
            unsigned a1 = psh[(qr + 8) * PSW + Lw + qc];
            unsigned a2 = psh[qr * PSW + Lw + qc + 4];
            unsigned a3 = psh[(qr + 8) * PSW + Lw + qc + 4];
            const float* vA0 = vt + (bufA * STG_L + 2 * qc) * VS;
            const float* vA1 = vA0 + VS;
            const float* vB0 = vt + (bufB * STG_L + 2 * qc) * VS;
            const float* vB1 = vB0 + VS;
#pragma unroll
            for (int t = 0; t < 4; t++) {
                int dd = d0w + t * 8 + qr;
                unsigned bb0 = pack_h2(vA0[dd], vA1[dd]);
                unsigned bb1 = pack_h2(vB0[dd], vB1[dd]);
                mma_f16(acc[t][0], acc[t][1], acc[t][2], acc[t][3],
                        a0, a1, a2, a3, bb0, bb1);
            }
            __syncthreads();
        }

        float* outp = g_partial + ((size_t)(b * NSLOT + c) * HH) * VSZ;
#pragma unroll
        for (int t = 0; t < 4; t++) {
            int d = d0w + t * 8 + 2 * qc;
            *(float2*)(outp + (size_t)qr * VSZ + d)       = make_float2(acc[t][0], acc[t][1]);
            *(float2*)(outp + (size_t)(qr + 8) * VSZ + d) = make_float2(acc[t][2], acc[t][3]);
        }
    }
}

// ============================================================
// K3: fused reduce + output projection.
// out[b,n] = (Wv[n,:] . sum_c partial[b,c,h,:]) / S[b,h] + bv[n]
// ============================================================
__global__ void __launch_bounds__(256) k_out(const float* __restrict__ Wv,
                                             const float* __restrict__ bv,
                                             float* __restrict__ out) {
    __shared__ float pvs[8 * VSZ];
    __shared__ float invS[8];
    int tid = threadIdx.x, lane = tid & 31, warp = tid >> 5;
    int n  = blockIdx.x * 8 + warp;
    int b0 = blockIdx.y * 8;
    int h  = (blockIdx.x * 8) >> 6;

    if (tid < 8) {
        const float* sp = g_s + ((size_t)(b0 + tid) * NSLOT) * HH + h;
        float S = 0.f;
#pragma unroll
        for (int c = 0; c < NSLOT; c++) S += sp[c * HH];
        invS[tid] = 1.0f / S;
    }

    float4* pv4 = (float4*)pvs;
    for (int i = tid; i < 8 * VSZ / 4; i += 256) {
        int bl = i >> 6, k4 = i & 63;
        const float4* src = (const float4*)(g_partial +
            ((size_t)((b0 + bl) * NSLOT) * HH + h) * VSZ) + k4;
        float4 s = make_float4(0.f, 0.f, 0.f, 0.f);
#pragma unroll
        for (int c = 0; c < NSLOT; c++) {
            float4 v = src[(size_t)c * HH * (VSZ / 4)];
            s.x += v.x; s.y += v.y; s.z += v.z; s.w += v.w;
        }
        pv4[i] = s;
    }
    __syncthreads();

    const float4* w4 = (const float4*)(Wv + (size_t)n * VSZ);
    float acc[8];
#pragma unroll
    for (int b = 0; b < 8; b++) acc[b] = 0.f;

#pragma unroll
    for (int it = 0; it < 2; it++) {
        int idx = it * 32 + lane;
        float4 w = __ldg(w4 + idx);
#pragma unroll
        for (int b = 0; b < 8; b++) {
            float4 p = pv4[b * (VSZ / 4) + idx];
            acc[b] += w.x * p.x + w.y * p.y + w.z * p.z + w.w * p.w;
        }
    }
#pragma unroll
    for (int b = 0; b < 8; b++) {
#pragma unroll
        for (int o = 16; o; o >>= 1) acc[b] += __shfl_xor_sync(0xffffffffu, acc[b], o);
    }
    if (lane == 0) {
        float bias = bv[n];
#pragma unroll
        for (int b = 0; b < 8; b++)
            out[(size_t)(b0 + b) * IN + n] = acc[b] * invS[b] + bias;
    }
}

// ============================================================
extern "C" void kernel_launch(void* const* d_in, const int* in_sizes, int n_in,
                              void* d_out, int out_size) {
    const float* query = (const float*)d_in[0];
    const float* key   = (const float*)d_in[1];
    const float* value = (const float*)d_in[2];
    const float* Wq    = (const float*)d_in[3];
    const float* bq    = (const float*)d_in[4];
    const float* Wv    = (const float*)d_in[5];
    const float* bv    = (const float*)d_in[6];
    float* out = (float*)d_out;

    cudaFuncSetAttribute(k_att, cudaFuncAttributeMaxDynamicSharedMemorySize, SMEM_BYTES);

    k_q<<<dim3(IN / 4, BB / 8), 256>>>(query, Wq, bq);
    k_att<<<dim3(NCHUNK, BB), 256, SMEM_BYTES>>>(key, value);
    k_out<<<dim3(IN / 8, BB / 8), 256>>>(Wv, bv, out);
}

// round 15
// speedup vs baseline: 1.4520x; 1.4520x over previous
#include <cuda_runtime.h>

#define BB   32
#define LL   4096
#define IN   1024
#define QSZ  64
#define VSZ  256
#define HH   16
#define NCHUNK 16          // k_att blocks per batch (l-chunks of 256)
#define LCH  256
#define NSLOT 16           // one partial slot per chunk

#define QS_STRIDE 68
#define PSW   132          // psh row stride in 32-bit words
#define STG_L 8            // l-rows per cp.async stage (phase B)
#define NSTG  (LCH/STG_L)  // 32
#define DEPTH 4            // phase-B stage buffers
#define VS    260          // padded f32 per v row
#define KTS   68           // padded words per key row (phase A staging)

// shared region: qs 1088 + psh 2112 + wsum 128 + union(kt 128*68=8704, vt 4*8*260=8320)
#define UNION_WORDS 8704
#define SMEM_WORDS (1088 + 2112 + 128 + UNION_WORDS)
#define SMEM_BYTES (SMEM_WORDS * 4)

// Scratch (__device__ globals; no allocation allowed)
__device__ float g_q[BB*IN];                     // 128 KB
__device__ float g_partial[BB*NSLOT*HH*VSZ];     // 8 MB (unnormalized)
__device__ float g_s[BB*NSLOT*HH];               // per-slot expsum
__device__ float g_pv[BB*HH*VSZ];                // normalized pv

// ---- mma helpers ----
__device__ __forceinline__ unsigned f2tf(float f) {
    unsigned u; asm("cvt.rna.tf32.f32 %0, %1;" : "=r"(u) : "f"(f)); return u;
}
__device__ __forceinline__ unsigned pack_h2(float lo, float hi) {
    unsigned d; asm("cvt.rn.f16x2.f32 %0, %1, %2;" : "=r"(d) : "f"(hi), "f"(lo)); return d;
}
__device__ __forceinline__ void mma_tf32(float& c0, float& c1, float& c2, float& c3,
                                         unsigned a0, unsigned a1, unsigned a2, unsigned a3,
                                         unsigned b0, unsigned b1) {
    asm("mma.sync.aligned.m16n8k8.row.col.f32.tf32.tf32.f32 "
        "{%0,%1,%2,%3}, {%4,%5,%6,%7}, {%8,%9}, {%0,%1,%2,%3};"
        : "+f"(c0), "+f"(c1), "+f"(c2), "+f"(c3)
        : "r"(a0), "r"(a1), "r"(a2), "r"(a3), "r"(b0), "r"(b1));
}
__device__ __forceinline__ void mma_f16(float& c0, float& c1, float& c2, float& c3,
                                        unsigned a0, unsigned a1, unsigned a2, unsigned a3,
                                        unsigned b0, unsigned b1) {
    asm("mma.sync.aligned.m16n8k16.row.col.f32.f16.f16.f32 "
        "{%0,%1,%2,%3}, {%4,%5,%6,%7}, {%8,%9}, {%0,%1,%2,%3};"
        : "+f"(c0), "+f"(c1), "+f"(c2), "+f"(c3)
        : "r"(a0), "r"(a1), "r"(a2), "r"(a3), "r"(b0), "r"(b1));
}
__device__ __forceinline__ void cp16(unsigned smem_addr, const void* gmem) {
    asm volatile("cp.async.cg.shared.global [%0], [%1], 16;" :: "r"(smem_addr), "l"(gmem));
}
__device__ __forceinline__ void cp_commit() {
    asm volatile("cp.async.commit_group;");
}
template <int N>
__device__ __forceinline__ void cp_wait() {
    asm volatile("cp.async.wait_group %0;" :: "n"(N));
}

// ============================================================
// K1: q[b,n] = query[b,:].Wq[n,:] + bq[n]
// R12 version (measured 12.96us): warp-per-n, 8 n x 8 b per block.
// ============================================================
__global__ void __launch_bounds__(256) k_q(const float* __restrict__ query,
                                           const float* __restrict__ Wq,
                                           const float* __restrict__ bq) {
    __shared__ float qsm[8 * IN];
    int tid = threadIdx.x, lane = tid & 31, warp = tid >> 5;
    int n  = blockIdx.x * 8 + warp;
    int b0 = blockIdx.y * 8;

    const float4* qg = (const float4*)(query + (size_t)b0 * IN);
    float4* qs4 = (float4*)qsm;
    for (int i = tid; i < 8 * IN / 4; i += 256) qs4[i] = __ldg(qg + i);
    __syncthreads();

    const float4* w4 = (const float4*)(Wq + (size_t)n * IN);
    float acc[8];
#pragma unroll
    for (int b = 0; b < 8; b++) acc[b] = 0.f;

#pragma unroll
    for (int it = 0; it < 8; it++) {
        int idx = it * 32 + lane;
        float4 w = __ldg(w4 + idx);
#pragma unroll
        for (int b = 0; b < 8; b++) {
            float4 q = qs4[b * (IN / 4) + idx];
            acc[b] += w.x * q.x + w.y * q.y + w.z * q.z + w.w * q.w;
        }
    }
#pragma unroll
    for (int b = 0; b < 8; b++) {
#pragma unroll
        for (int o = 16; o; o >>= 1) acc[b] += __shfl_xor_sync(0xffffffffu, acc[b], o);
    }
    if (lane == 0) {
        float bias = bq[n];
#pragma unroll
        for (int b = 0; b < 8; b++)
            g_q[(size_t)(b0 + b) * IN + n] = acc[b] + bias;
    }
}

// ============================================================
// K2: R13 version verbatim — scores (tf32 MMA, smem-staged key) + exp
//     + pv (fp16 MMA, cp.async pipeline).
// ============================================================
__global__ void __launch_bounds__(256) k_att(const float* __restrict__ key,
                                             const float* __restrict__ value) {
    extern __shared__ float smx[];
    unsigned* qs   = (unsigned*)smx;           // [16 * 68] tf32 q
    unsigned* psh  = qs + HH * QS_STRIDE;      // [16 * 132] fp16x2 weights
    float*    wsum = (float*)(psh + HH * PSW); // [8*16]
    float*    vt   = wsum + 8 * HH;            // union: vt (phase B) / kt (phase A)
    unsigned* kt   = (unsigned*)vt;            // [128 * 68] staged key (tf32)

    int b = blockIdx.y, c = blockIdx.x;
    int tid = threadIdx.x, lane = tid & 31, w = tid >> 5;
    int qr = lane >> 2, qc = lane & 3;

    for (int i = tid; i < HH * QSZ; i += 256) {
        int h = i >> 6, d = i & 63;
        qs[h * QS_STRIDE + d] = f2tf(g_q[(size_t)b * IN + i]);
    }
    __syncthreads();

    // ---- Phase A: scores = q @ key^T (tf32), two staged halves ----
    {
        const float* kb = key + ((size_t)b * LL + (size_t)c * LCH) * QSZ;
        float acc[4][4];
#pragma unroll
        for (int t = 0; t < 4; t++)
#pragma unroll
            for (int j = 0; j < 4; j++) acc[t][j] = 0.f;

        float slo = 0.f, shi = 0.f;

#pragma unroll
        for (int half = 0; half < 2; half++) {
            const float4* kb4 = (const float4*)(kb + (size_t)half * 128 * QSZ);
#pragma unroll
            for (int it = 0; it < 8; it++) {
                int i = it * 256 + tid;
                int row = i >> 4, c4 = i & 15;
                float4 kk = __ldg(kb4 + i);
                unsigned* dst = kt + row * KTS + c4 * 4;
                dst[0] = f2tf(kk.x); dst[1] = f2tf(kk.y);
                dst[2] = f2tf(kk.z); dst[3] = f2tf(kk.w);
            }
            __syncthreads();

#pragma unroll
            for (int k0 = 0; k0 < QSZ; k0 += 8) {
                unsigned a0 = qs[qr * QS_STRIDE + k0 + qc];
                unsigned a1 = qs[(qr + 8) * QS_STRIDE + k0 + qc];
                unsigned a2 = qs[qr * QS_STRIDE + k0 + qc + 4];
                unsigned a3 = qs[(qr + 8) * QS_STRIDE + k0 + qc + 4];
#pragma unroll
                for (int tt = 0; tt < 2; tt++) {
                    int lr = w * 16 + tt * 8 + qr;
                    unsigned b0 = kt[lr * KTS + k0 + qc];
                    unsigned b1 = kt[lr * KTS + k0 + qc + 4];
                    int t = half * 2 + tt;
                    mma_tf32(acc[t][0], acc[t][1], acc[t][2], acc[t][3],
                             a0, a1, a2, a3, b0, b1);
                }
            }

#pragma unroll
            for (int tt = 0; tt < 2; tt++) {
                int t = half * 2 + tt;
                int lb = half * 128 + w * 16 + tt * 8 + 2 * qc;
                float e0 = __expf(acc[t][0] * 0.125f);
                float e1 = __expf(acc[t][1] * 0.125f);
                float e2 = __expf(acc[t][2] * 0.125f);
                float e3 = __expf(acc[t][3] * 0.125f);
                slo += e0 + e1;
                shi += e2 + e3;
                psh[qr * PSW + (lb >> 1)]       = pack_h2(e0, e1);
                psh[(qr + 8) * PSW + (lb >> 1)] = pack_h2(e2, e3);
            }
            __syncthreads();
        }

        slo += __shfl_xor_sync(0xffffffffu, slo, 1);
        slo += __shfl_xor_sync(0xffffffffu, slo, 2);
        shi += __shfl_xor_sync(0xffffffffu, shi, 1);
        shi += __shfl_xor_sync(0xffffffffu, shi, 2);
        if (qc == 0) {
            wsum[w * HH + qr]     = slo;
            wsum[w * HH + qr + 8] = shi;
        }
    }
    __syncthreads();
    if (tid < HH) {
        float S = 0.f;
#pragma unroll
        for (int i = 0; i < 8; i++) S += wsum[i * HH + tid];
        g_s[((size_t)b * NSLOT + c) * HH + tid] = S;
    }

    // ---- Phase B: pv = p @ v (fp16 MMA), 16 iterations of 16 l ----
    {
        int d0w = w * 32;
        const float* vb = value + ((size_t)b * LL + (size_t)c * LCH) * VSZ;
        unsigned vt_u = (unsigned)__cvta_generic_to_shared(vt);
        int r0 = tid >> 6, c4a = tid & 63;
        int r1 = r0 + 4;

        float acc[4][4];
#pragma unroll
        for (int t = 0; t < 4; t++)
#pragma unroll
            for (int j = 0; j < 4; j++) acc[t][j] = 0.f;

#pragma unroll
        for (int s = 0; s < 2; s++) {
            unsigned base = vt_u + (unsigned)(s * STG_L * VS) * 4u;
            cp16(base + (unsigned)(r0 * VS + c4a * 4) * 4u,
                 vb + (size_t)(s * STG_L + r0) * VSZ + c4a * 4);
            cp16(base + (unsigned)(r1 * VS + c4a * 4) * 4u,
                 vb + (size_t)(s * STG_L + r1) * VSZ + c4a * 4);
            cp_commit();
        }

        for (int si = 0; si < NSTG / 2; si++) {
#pragma unroll
            for (int ss = 0; ss < 2; ss++) {
                int s = 2 * si + 2 + ss;
                if (s < NSTG) {
                    unsigned base = vt_u + (unsigned)((s & 3) * STG_L * VS) * 4u;
                    cp16(base + (unsigned)(r0 * VS + c4a * 4) * 4u,
                         vb + (size_t)(s * STG_L + r0) * VSZ + c4a * 4);
                    cp16(base + (unsigned)(r1 * VS + c4a * 4) * 4u,
                         vb + (size_t)(s * STG_L + r1) * VSZ + c4a * 4);
                }
                cp_commit();
            }
            cp_wait<2>();
            __syncthreads();

            int bufA = (2 * si) & 3, bufB = (2 * si + 1) & 3;
            int Lw = si * 8;
            unsigned a0 = psh[qr * PSW + Lw + qc];
            unsigned a1 = psh[(qr + 8) * PSW + Lw + qc];
            unsigned a2 = psh[qr * PSW + Lw + qc + 4];
            unsigned a3 = psh[(qr + 8) * PSW + Lw + qc + 4];
            const float* vA0 = vt + (bufA * STG_L + 2 * qc) * VS;
            const float* vA1 = vA0 + VS;
            const float* vB0 = vt + (bufB * STG_L + 2 * qc) * VS;
            const float* vB1 = vB0 + VS;
#pragma unroll
            for (int t = 0; t < 4; t++) {
                int dd = d0w + t * 8 + qr;
                unsigned bb0 = pack_h2(vA0[dd], vA1[dd]);
                unsigned bb1 = pack_h2(vB0[dd], vB1[dd]);
                mma_f16(acc[t][0], acc[t][1], acc[t][2], acc[t][3],
                        a0, a1, a2, a3, bb0, bb1);
            }
            __syncthreads();
        }

        float* outp = g_partial + ((size_t)(b * NSLOT + c) * HH) * VSZ;
#pragma unroll
        for (int t = 0; t < 4; t++) {
            int d = d0w + t * 8 + 2 * qc;
            *(float2*)(outp + (size_t)qr * VSZ + d)       = make_float2(acc[t][0], acc[t][1]);
            *(float2*)(outp + (size_t)(qr + 8) * VSZ + d) = make_float2(acc[t][2], acc[t][3]);
        }
    }
}

// ============================================================
// K3: combine 16 slots: sum partials (read once), sum S, normalize.
// ============================================================
__global__ void __launch_bounds__(256) k_red() {
    int g = blockIdx.x * 256 + threadIdx.x;
    int d2 = g & 127;
    int h  = (g >> 7) & (HH - 1);
    int b  = g >> 11;

    const float* sp = g_s + (size_t)b * NSLOT * HH + h;
    float S = 0.f;
#pragma unroll
    for (int c = 0; c < NSLOT; c++) S += sp[c * HH];

    const float2* pp = (const float2*)(g_partial + ((size_t)b * NSLOT * HH + h) * VSZ) + d2;
    float2 pv = make_float2(0.f, 0.f);
#pragma unroll
    for (int c = 0; c < NSLOT; c++) {
        float2 v = pp[(size_t)c * HH * (VSZ / 2)];
        pv.x += v.x;
        pv.y += v.y;
    }
    float inv = 1.0f / S;
    ((float2*)(g_pv + (size_t)(b * HH + h) * VSZ))[d2] = make_float2(pv.x * inv, pv.y * inv);
}

// ============================================================
// K4: out[b,n] = Wv[n,:].pv[b, n>>6, :] + bv[n]
// ============================================================
__global__ void __launch_bounds__(256) k_out(const float* __restrict__ Wv,
                                             const float* __restrict__ bv,
                                             float* __restrict__ out) {
    __shared__ float pvs[8 * VSZ];
    int tid = threadIdx.x, lane = tid & 31, warp = tid >> 5;
    int n  = blockIdx.x * 8 + warp;
    int b0 = blockIdx.y * 8;
    int h  = (blockIdx.x * 8) >> 6;

    float4* pv4 = (float4*)pvs;
    for (int i = tid; i < 8 * VSZ / 4; i += 256) {
        int bl = i / (VSZ / 4), k4 = i % (VSZ / 4);
        pv4[i] = ((const float4*)(g_pv + (size_t)((b0 + bl) * HH + h) * VSZ))[k4];
    }
    __syncthreads();

    const float4* w4 = (const float4*)(Wv + (size_t)n * VSZ);
    float acc[8];
#pragma unroll
    for (int b = 0; b < 8; b++) acc[b] = 0.f;

#pragma unroll
    for (int it = 0; it < 2; it++) {
        int idx = it * 32 + lane;
        float4 w = __ldg(w4 + idx);
#pragma unroll
        for (int b = 0; b < 8; b++) {
            float4 p = pv4[b * (VSZ / 4) + idx];
            acc[b] += w.x * p.x + w.y * p.y + w.z * p.z + w.w * p.w;
        }
    }
#pragma unroll
    for (int b = 0; b < 8; b++) {
#pragma unroll
        for (int o = 16; o; o >>= 1) acc[b] += __shfl_xor_sync(0xffffffffu, acc[b], o);
    }
    if (lane == 0) {
        float bias = bv[n];
#pragma unroll
        for (int b = 0; b < 8; b++)
            out[(size_t)(b0 + b) * IN + n] = acc[b] + bias;
    }
}

// ============================================================
extern "C" void kernel_launch(void* const* d_in, const int* in_sizes, int n_in,
                              void* d_out, int out_size) {
    const float* query = (const float*)d_in[0];
    const float* key   = (const float*)d_in[1];
    const float* value = (const float*)d_in[2];
    const float* Wq    = (const float*)d_in[3];
    const float* bq    = (const float*)d_in[4];
    const float* Wv    = (const float*)d_in[5];
    const float* bv    = (const float*)d_in[6];
    float* out = (float*)d_out;

    cudaFuncSetAttribute(k_att, cudaFuncAttributeMaxDynamicSharedMemorySize, SMEM_BYTES);

    k_q<<<dim3(IN / 8, BB / 8), 256>>>(query, Wq, bq);
    k_att<<<dim3(NCHUNK, BB), 256, SMEM_BYTES>>>(key, value);
    k_red<<<BB * HH * (VSZ / 2) / 256, 256>>>();
    k_out<<<dim3(IN / 8, BB / 8), 256>>>(Wv, bv, out);
}

// round 17
// speedup vs baseline: 1.5720x; 1.0826x over previous
#include <cuda_runtime.h>

#define BB   32
#define LL   4096
#define IN   1024
#define QSZ  64
#define VSZ  256
#define HH   16
#define NCHUNK 16          // k_att blocks per batch (l-chunks of 256)
#define LCH  256
#define NSLOT 16           // one partial slot per chunk

#define QS_STRIDE 68
#define PSW   132          // psh row stride in 32-bit words
#define STG_L 8            // l-rows per cp.async stage (phase B)
#define NSTG  (LCH/STG_L)  // 32
#define DEPTH 4            // phase-B stage buffers
#define VS    260          // padded f32 per v row
#define KTS   68           // padded words per key row (phase A staging)
#define QMS   260          // k_qm staged query row stride (words)
#define NQP   8            // q-projection partial slots (4 kc x 2 k-subs)

// shared region: qs 1088 + psh 2112 + wsum 128 + union(kt 128*68=8704, vt 4*8*260=8320)
#define UNION_WORDS 8704
#define SMEM_WORDS (1088 + 2112 + 128 + UNION_WORDS)
#define SMEM_BYTES (SMEM_WORDS * 4)

// Scratch (__device__ globals; no allocation allowed)
__device__ float g_qp[NQP*BB*IN];                // 1 MB: 8 k-partials of q
__device__ float g_partial[BB*NSLOT*HH*VSZ];     // 8 MB (unnormalized)
__device__ float g_s[BB*NSLOT*HH];               // per-slot expsum
__device__ float g_pv[BB*HH*VSZ];                // normalized pv

// ---- mma helpers ----
__device__ __forceinline__ unsigned f2tf(float f) {
    unsigned u; asm("cvt.rna.tf32.f32 %0, %1;" : "=r"(u) : "f"(f)); return u;
}
__device__ __forceinline__ unsigned pack_h2(float lo, float hi) {
    unsigned d; asm("cvt.rn.f16x2.f32 %0, %1, %2;" : "=r"(d) : "f"(hi), "f"(lo)); return d;
}
__device__ __forceinline__ void mma_tf32(float& c0, float& c1, float& c2, float& c3,
                                         unsigned a0, unsigned a1, unsigned a2, unsigned a3,
                                         unsigned b0, unsigned b1) {
    asm("mma.sync.aligned.m16n8k8.row.col.f32.tf32.tf32.f32 "
        "{%0,%1,%2,%3}, {%4,%5,%6,%7}, {%8,%9}, {%0,%1,%2,%3};"
        : "+f"(c0), "+f"(c1), "+f"(c2), "+f"(c3)
        : "r"(a0), "r"(a1), "r"(a2), "r"(a3), "r"(b0), "r"(b1));
}
__device__ __forceinline__ void mma_f16(float& c0, float& c1, float& c2, float& c3,
                                        unsigned a0, unsigned a1, unsigned a2, unsigned a3,
                                        unsigned b0, unsigned b1) {
    asm("mma.sync.aligned.m16n8k16.row.col.f32.f16.f16.f32 "
        "{%0,%1,%2,%3}, {%4,%5,%6,%7}, {%8,%9}, {%0,%1,%2,%3};"
        : "+f"(c0), "+f"(c1), "+f"(c2), "+f"(c3)
        : "r"(a0), "r"(a1), "r"(a2), "r"(a3), "r"(b0), "r"(b1));
}
__device__ __forceinline__ void cp16(unsigned smem_addr, const void* gmem) {
    asm volatile("cp.async.cg.shared.global [%0], [%1], 16;" :: "r"(smem_addr), "l"(gmem));
}
__device__ __forceinline__ void cp_commit() {
    asm volatile("cp.async.commit_group;");
}
template <int N>
__device__ __forceinline__ void cp_wait() {
    asm volatile("cp.async.wait_group %0;" :: "n"(N));
}

// ============================================================
// K1: q-projection as tf32 MMA split-K GEMM.
// qp[kc*2 + ksub][b, n] = query[b, kc*256+ksub*128 : +128] @ Wq[n, same]^T
// (+bq in slot 0). grid (32 n-chunks, 4 k-chunks) x 256.
// Warp = (n-tile 8) x (k-sub 128). DISTINCT partial slot per (kc, ksub)
// -> no write races (R16 bug fix).
// ============================================================
__global__ void __launch_bounds__(256) k_qm(const float* __restrict__ query,
                                            const float* __restrict__ Wq,
                                            const float* __restrict__ bq) {
    __shared__ unsigned qsm[32 * QMS];          // staged query chunk (tf32)
    int tid = threadIdx.x, lane = tid & 31, w = tid >> 5;
    int qr = lane >> 2, qc = lane & 3;
    int nblk = blockIdx.x;                       // n0_blk = nblk*32
    int kc   = blockIdx.y;                       // k base kc*256

    // stage query[32][kc*256 .. +256] as tf32 (coalesced float4)
    const float4* qg = (const float4*)(query + kc * 256);
#pragma unroll
    for (int it = 0; it < 8; it++) {
        int i = it * 256 + tid;                  // 0..2047
        int r = i >> 6, c4 = i & 63;
        float4 v = __ldg(qg + (size_t)r * (IN / 4) + c4);
        unsigned* dst = qsm + r * QMS + c4 * 4;
        dst[0] = f2tf(v.x); dst[1] = f2tf(v.y);
        dst[2] = f2tf(v.z); dst[3] = f2tf(v.w);
    }
    __syncthreads();

    int ksub = w >> 2;
    int n0 = nblk * 32 + (w & 3) * 8;
    int ks = ksub * 128;                         // k-sub within the 256 chunk
    const float* wqb = Wq + (size_t)kc * 256;

    float acc[2][4];
#pragma unroll
    for (int mt = 0; mt < 2; mt++)
#pragma unroll
        for (int j = 0; j < 4; j++) acc[mt][j] = 0.f;

#pragma unroll
    for (int k0 = 0; k0 < 128; k0 += 8) {
        int kk = ks + k0;
        unsigned b0 = f2tf(__ldg(wqb + (size_t)(n0 + qr) * IN + kk + qc));
        unsigned b1 = f2tf(__ldg(wqb + (size_t)(n0 + qr) * IN + kk + qc + 4));
#pragma unroll
        for (int mt = 0; mt < 2; mt++) {
            unsigned a0 = qsm[(mt * 16 + qr) * QMS + kk + qc];
            unsigned a1 = qsm[(mt * 16 + qr + 8) * QMS + kk + qc];
            unsigned a2 = qsm[(mt * 16 + qr) * QMS + kk + qc + 4];
            unsigned a3 = qsm[(mt * 16 + qr + 8) * QMS + kk + qc + 4];
            mma_tf32(acc[mt][0], acc[mt][1], acc[mt][2], acc[mt][3],
                     a0, a1, a2, a3, b0, b1);
        }
    }

    int slot = kc * 2 + ksub;
    int n = n0 + 2 * qc;
    float bias0 = 0.f, bias1 = 0.f;
    if (slot == 0) { bias0 = bq[n]; bias1 = bq[n + 1]; }
    float* qp = g_qp + (size_t)slot * BB * IN;
#pragma unroll
    for (int mt = 0; mt < 2; mt++) {
        int brow = mt * 16 + qr;
        *(float2*)(qp + (size_t)brow * IN + n) =
            make_float2(acc[mt][0] + bias0, acc[mt][1] + bias1);
        *(float2*)(qp + (size_t)(brow + 8) * IN + n) =
            make_float2(acc[mt][2] + bias0, acc[mt][3] + bias1);
    }
}

// ============================================================
// K2: scores (tf32 MMA, smem-staged key) + exp + pv (fp16 MMA,
//     cp.async pipeline). qs loader sums the 8 k-partials of q.
// ============================================================
__global__ void __launch_bounds__(256) k_att(const float* __restrict__ key,
                                             const float* __restrict__ value) {
    extern __shared__ float smx[];
    unsigned* qs   = (unsigned*)smx;           // [16 * 68] tf32 q
    unsigned* psh  = qs + HH * QS_STRIDE;      // [16 * 132] fp16x2 weights
    float*    wsum = (float*)(psh + HH * PSW); // [8*16]
    float*    vt   = wsum + 8 * HH;            // union: vt (phase B) / kt (phase A)
    unsigned* kt   = (unsigned*)vt;            // [128 * 68] staged key (tf32)

    int b = blockIdx.y, c = blockIdx.x;
    int tid = threadIdx.x, lane = tid & 31, w = tid >> 5;
    int qr = lane >> 2, qc = lane & 3;

    for (int i = tid; i < HH * QSZ; i += 256) {
        int h = i >> 6, d = i & 63;
        size_t off = (size_t)b * IN + i;
        float s = 0.f;
#pragma unroll
        for (int p = 0; p < NQP; p++) s += g_qp[(size_t)p * BB * IN + off];
        qs[h * QS_STRIDE + d] = f2tf(s);
    }
    __syncthreads();

    // ---- Phase A: scores = q @ key^T (tf32), two staged halves ----
    {
        const float* kb = key + ((size_t)b * LL + (size_t)c * LCH) * QSZ;
        float acc[4][4];
#pragma unroll
        for (int t = 0; t < 4; t++)
#pragma unroll
            for (int j = 0; j < 4; j++) acc[t][j] = 0.f;

        float slo = 0.f, shi = 0.f;

#pragma unroll
        for (int half = 0; half < 2; half++) {
            const float4* kb4 = (const float4*)(kb + (size_t)half * 128 * QSZ);
#pragma unroll
            for (int it = 0; it < 8; it++) {
                int i = it * 256 + tid;
                int row = i >> 4, c4 = i & 15;
                float4 kk = __ldg(kb4 + i);
                unsigned* dst = kt + row * KTS + c4 * 4;
                dst[0] = f2tf(kk.x); dst[1] = f2tf(kk.y);
                dst[2] = f2tf(kk.z); dst[3] = f2tf(kk.w);
            }
            __syncthreads();

#pragma unroll
            for (int k0 = 0; k0 < QSZ; k0 += 8) {
                unsigned a0 = qs[qr * QS_STRIDE + k0 + qc];
                unsigned a1 = qs[(qr + 8) * QS_STRIDE + k0 + qc];
                unsigned a2 = qs[qr * QS_STRIDE + k0 + qc + 4];
                unsigned a3 = qs[(qr + 8) * QS_STRIDE + k0 + qc + 4];
#pragma unroll
                for (int tt = 0; tt < 2; tt++) {
                    int lr = w * 16 + tt * 8 + qr;
                    unsigned b0 = kt[lr * KTS + k0 + qc];
                    unsigned b1 = kt[lr * KTS + k0 + qc + 4];
                    int t = half * 2 + tt;
                    mma_tf32(acc[t][0], acc[t][1], acc[t][2], acc[t][3],
                             a0, a1, a2, a3, b0, b1);
                }
            }

#pragma unroll
            for (int tt = 0; tt < 2; tt++) {
                int t = half * 2 + tt;
                int lb = half * 128 + w * 16 + tt * 8 + 2 * qc;
                float e0 = __expf(acc[t][0] * 0.125f);
                float e1 = __expf(acc[t][1] * 0.125f);
                float e2 = __expf(acc[t][2] * 0.125f);
                float e3 = __expf(acc[t][3] * 0.125f);
                slo += e0 + e1;
                shi += e2 + e3;
                psh[qr * PSW + (lb >> 1)]       = pack_h2(e0, e1);
                psh[(qr + 8) * PSW + (lb >> 1)] = pack_h2(e2, e3);
            }
            __syncthreads();
        }

        slo += __shfl_xor_sync(0xffffffffu, slo, 1);
        slo += __shfl_xor_sync(0xffffffffu, slo, 2);
        shi += __shfl_xor_sync(0xffffffffu, shi, 1);
        shi += __shfl_xor_sync(0xffffffffu, shi, 2);
        if (qc == 0) {
            wsum[w * HH + qr]     = slo;
            wsum[w * HH + qr + 8] = shi;
        }
    }
    __syncthreads();
    if (tid < HH) {
        float S = 0.f;
#pragma unroll
        for (int i = 0; i < 8; i++) S += wsum[i * HH + tid];
        g_s[((size_t)b * NSLOT + c) * HH + tid] = S;
    }

    // ---- Phase B: pv = p @ v (fp16 MMA), 16 iterations of 16 l ----
    {
        int d0w = w * 32;
        const float* vb = value + ((size_t)b * LL + (size_t)c * LCH) * VSZ;
        unsigned vt_u = (unsigned)__cvta_generic_to_shared(vt);
        int r0 = tid >> 6, c4a = tid & 63;
        int r1 = r0 + 4;

        float acc[4][4];
#pragma unroll
        for (int t = 0; t < 4; t++)
#pragma unroll
            for (int j = 0; j < 4; j++) acc[t][j] = 0.f;

#pragma unroll
        for (int s = 0; s < 2; s++) {
            unsigned base = vt_u + (unsigned)(s * STG_L * VS) * 4u;
            cp16(base + (unsigned)(r0 * VS + c4a * 4) * 4u,
                 vb + (size_t)(s * STG_L + r0) * VSZ + c4a * 4);
            cp16(base + (unsigned)(r1 * VS + c4a * 4) * 4u,
                 vb + (size_t)(s * STG_L + r1) * VSZ + c4a * 4);
            cp_commit();
        }

        for (int si = 0; si < NSTG / 2; si++) {
#pragma unroll
            for (int ss = 0; ss < 2; ss++) {
                int s = 2 * si + 2 + ss;
                if (s < NSTG) {
                    unsigned base = vt_u + (unsigned)((s & 3) * STG_L * VS) * 4u;
                    cp16(base + (unsigned)(r0 * VS + c4a * 4) * 4u,
                         vb + (size_t)(s * STG_L + r0) * VSZ + c4a * 4);
                    cp16(base + (unsigned)(r1 * VS + c4a * 4) * 4u,
                         vb + (size_t)(s * STG_L + r1) * VSZ + c4a * 4);
                }
                cp_commit();
            }
            cp_wait<2>();
            __syncthreads();

            int bufA = (2 * si) & 3, bufB = (2 * si + 1) & 3;
            int Lw = si * 8;
            unsigned a0 = psh[qr * PSW + Lw + qc];
            unsigned a1 = psh[(qr + 8) * PSW + Lw + qc];
            unsigned a2 = psh[qr * PSW + Lw + qc + 4];
            unsigned a3 = psh[(qr + 8) * PSW + Lw + qc + 4];
            const float* vA0 = vt + (bufA * STG_L + 2 * qc) * VS;
            const float* vA1 = vA0 + VS;
            const float* vB0 = vt + (bufB * STG_L + 2 * qc) * VS;
            const float* vB1 = vB0 + VS;
#pragma unroll
            for (int t = 0; t < 4; t++) {
                int dd = d0w + t * 8 + qr;
                unsigned bb0 = pack_h2(vA0[dd], vA1[dd]);
                unsigned bb1 = pack_h2(vB0[dd], vB1[dd]);
                mma_f16(acc[t][0], acc[t][1], acc[t][2], acc[t][3],
                        a0, a1, a2, a3, bb0, bb1);
            }
            __syncthreads();
        }

        float* outp = g_partial + ((size_t)(b * NSLOT + c) * HH) * VSZ;
#pragma unroll
        for (int t = 0; t < 4; t++) {
            int d = d0w + t * 8 + 2 * qc;
            *(float2*)(outp + (size_t)qr * VSZ + d)       = make_float2(acc[t][0], acc[t][1]);
            *(float2*)(outp + (size_t)(qr + 8) * VSZ + d) = make_float2(acc[t][2], acc[t][3]);
        }
    }
}

// ============================================================
// K3: combine 16 slots: sum partials (read once), sum S, normalize.
// ============================================================
__global__ void __launch_bounds__(256) k_red() {
    int g = blockIdx.x * 256 + threadIdx.x;
    int d2 = g & 127;
    int h  = (g >> 7) & (HH - 1);
    int b  = g >> 11;

    const float* sp = g_s + (size_t)b * NSLOT * HH + h;
    float S = 0.f;
#pragma unroll
    for (int c = 0; c < NSLOT; c++) S += sp[c * HH];

    const float2* pp = (const float2*)(g_partial + ((size_t)b * NSLOT * HH + h) * VSZ) + d2;
    float2 pv = make_float2(0.f, 0.f);
#pragma unroll
    for (int c = 0; c < NSLOT; c++) {
        float2 v = pp[(size_t)c * HH * (VSZ / 2)];
        pv.x += v.x;
        pv.y += v.y;
    }
    float inv = 1.0f / S;
    ((float2*)(g_pv + (size_t)(b * HH + h) * VSZ))[d2] = make_float2(pv.x * inv, pv.y * inv);
}

// ============================================================
// K4: out[b,n] = Wv[n,:].pv[b, n>>6, :] + bv[n]
// ============================================================
__global__ void __launch_bounds__(256) k_out(const float* __restrict__ Wv,
                                             const float* __restrict__ bv,
                                             float* __restrict__ out) {
    __shared__ float pvs[8 * VSZ];
    int tid = threadIdx.x, lane = tid & 31, warp = tid >> 5;
    int n  = blockIdx.x * 8 + warp;
    int b0 = blockIdx.y * 8;
    int h  = (blockIdx.x * 8) >> 6;

    float4* pv4 = (float4*)pvs;
    for (int i = tid; i < 8 * VSZ / 4; i += 256) {
        int bl = i / (VSZ / 4), k4 = i % (VSZ / 4);
        pv4[i] = ((const float4*)(g_pv + (size_t)((b0 + bl) * HH + h) * VSZ))[k4];
    }
    __syncthreads();

    const float4* w4 = (const float4*)(Wv + (size_t)n * VSZ);
    float acc[8];
#pragma unroll
    for (int b = 0; b < 8; b++) acc[b] = 0.f;

#pragma unroll
    for (int it = 0; it < 2; it++) {
        int idx = it * 32 + lane;
        float4 w = __ldg(w4 + idx);
#pragma unroll
        for (int b = 0; b < 8; b++) {
            float4 p = pv4[b * (VSZ / 4) + idx];
            acc[b] += w.x * p.x + w.y * p.y + w.z * p.z + w.w * p.w;
        }
    }
#pragma unroll
    for (int b = 0; b < 8; b++) {
#pragma unroll
        for (int o = 16; o; o >>= 1) acc[b] += __shfl_xor_sync(0xffffffffu, acc[b], o);
    }
    if (lane == 0) {
        float bias = bv[n];
#pragma unroll
        for (int b = 0; b < 8; b++)
            out[(size_t)(b0 + b) * IN + n] = acc[b] + bias;
    }
}

// ============================================================
extern "C" void kernel_launch(void* const* d_in, const int* in_sizes, int n_in,
                              void* d_out, int out_size) {
    const float* query = (const float*)d_in[0];
    const float* key   = (const float*)d_in[1];
    const float* value = (const float*)d_in[2];
    const float* Wq    = (const float*)d_in[3];
    const float* bq    = (const float*)d_in[4];
    const float* Wv    = (const float*)d_in[5];
    const float* bv    = (const float*)d_in[6];
    float* out = (float*)d_out;

    cudaFuncSetAttribute(k_att, cudaFuncAttributeMaxDynamicSharedMemorySize, SMEM_BYTES);

    k_qm<<<dim3(32, 4), 256>>>(query, Wq, bq);
    k_att<<<dim3(NCHUNK, BB), 256, SMEM_BYTES>>>(key, value);
    k_red<<<BB * HH * (VSZ / 2) / 256, 256>>>();
    k_out<<<dim3(IN / 8, BB / 8), 256>>>(Wv, bv, out);
}